// round 6
// baseline (speedup 1.0000x reference)
#include <cuda_runtime.h>
#include <cuda_bf16.h>
#include <math.h>
#include <stdint.h>

// Problem constants
#define B_  2
#define N_  2048
#define D_  1024
#define H_  16
#define DH_ 64
#define E3_ 192
#define J3_ 3072
#define M_  4096

// ---------------------------------------------------------------------------
// Scratch (device globals)
// ---------------------------------------------------------------------------
__device__ float g_attn[(size_t)B_*H_*N_*N_];

__device__ __nv_bfloat16 g_xhi [(size_t)M_*D_];
__device__ __nv_bfloat16 g_xlo [(size_t)M_*D_];
__device__ __nv_bfloat16 g_wqhi[(size_t)J3_*D_];
__device__ __nv_bfloat16 g_wqlo[(size_t)J3_*D_];
__device__ __nv_bfloat16 g_wphi[(size_t)D_*D_];
__device__ __nv_bfloat16 g_wplo[(size_t)D_*D_];
__device__ __nv_bfloat16 g_sahi[(size_t)M_*D_];
__device__ __nv_bfloat16 g_salo[(size_t)M_*D_];

__device__ __nv_bfloat16 g_qh[(size_t)B_*H_*N_*DH_];
__device__ __nv_bfloat16 g_ql[(size_t)B_*H_*N_*DH_];
__device__ __nv_bfloat16 g_kh[(size_t)B_*H_*N_*DH_];
__device__ __nv_bfloat16 g_kl[(size_t)B_*H_*N_*DH_];
__device__ __nv_bfloat16 g_vth[(size_t)B_*H_*DH_*N_];
__device__ __nv_bfloat16 g_vtl[(size_t)B_*H_*DH_*N_];

__device__ __nv_bfloat16 g_pbh[(size_t)B_*H_*N_*N_];
__device__ __nv_bfloat16 g_pbl[(size_t)B_*H_*N_*N_];

// ---------------------------------------------------------------------------
// Helpers
// ---------------------------------------------------------------------------
__device__ __forceinline__ uint32_t smem_u32(const void* p) {
    uint32_t a;
    asm("{ .reg .u64 t; cvta.to.shared.u64 t, %1; cvt.u32.u64 %0, t; }"
        : "=r"(a) : "l"(p));
    return a;
}

#define LDM4(r, addr)                                                         \
    asm volatile("ldmatrix.sync.aligned.m8n8.x4.shared.b16 {%0,%1,%2,%3}, [%4];" \
        : "=r"((r)[0]), "=r"((r)[1]), "=r"((r)[2]), "=r"((r)[3])              \
        : "r"(addr))

#define MMA_BF16(c, a, b0, b1)                                                \
    asm volatile("mma.sync.aligned.m16n8k16.row.col.f32.bf16.bf16.f32 "       \
        "{%0,%1,%2,%3}, {%4,%5,%6,%7}, {%8,%9}, {%0,%1,%2,%3};"               \
        : "+f"((c)[0]), "+f"((c)[1]), "+f"((c)[2]), "+f"((c)[3])              \
        : "r"((a)[0]), "r"((a)[1]), "r"((a)[2]), "r"((a)[3]), "r"(b0), "r"(b1))

#define CP16(dst, src)                                                        \
    asm volatile("cp.async.cg.shared.global [%0], [%1], 16;"                  \
        :: "r"(dst), "l"(src))
#define CP_COMMIT() asm volatile("cp.async.commit_group;" ::: "memory")
#define CP_WAIT0()  asm volatile("cp.async.wait_group 0;" ::: "memory")
#define CP_WAIT1()  asm volatile("cp.async.wait_group 1;" ::: "memory")

__device__ __forceinline__ void bf_split(float v, __nv_bfloat16& h, __nv_bfloat16& l) {
    h = __float2bfloat16(v);
    l = __float2bfloat16(v - __bfloat162float(h));
}

// ---------------------------------------------------------------------------
// split kernels
// ---------------------------------------------------------------------------
__global__ __launch_bounds__(256) void split_kernel(
    const float* __restrict__ in, __nv_bfloat16* __restrict__ hi,
    __nv_bfloat16* __restrict__ lo, int n)
{
    int i = blockIdx.x * 256 + threadIdx.x;
    if (i < n) {
        float v = in[i];
        __nv_bfloat16 h, l; bf_split(v, h, l);
        hi[i] = h; lo[i] = l;
    }
}

__global__ __launch_bounds__(256) void split_wqkv_kernel(
    const float* __restrict__ W, __nv_bfloat16* __restrict__ hi,
    __nv_bfloat16* __restrict__ lo)
{
    int idx = blockIdx.x * 256 + threadIdx.x;
    if (idx >= J3_ * D_) return;
    int j = idx >> 10, d = idx & 1023;
    int h = j / E3_, e = j % E3_;
    float v = W[((size_t)h * D_ + d) * E3_ + e];
    __nv_bfloat16 vh, vl; bf_split(v, vh, vl);
    hi[idx] = vh; lo[idx] = vl;
}

// ---------------------------------------------------------------------------
// gemm_pipe: 2-stage cp.async pipelined split-bf16 GEMM, K=1024, chunk 32.
// CTA 128x128, 8 warps (2x4), warp tile 64x32.
// MMA issue is term-major over mt-pairs: >=8 independent MMAs between any
// accumulator reuse (hides HMMA latency; fixes the R4/R5 tensor=50% ceiling).
// ---------------------------------------------------------------------------
#define GP_LDS 40
#define GP_AH 0
#define GP_AL 10240
#define GP_BH 20480
#define GP_BL 30720
#define GP_STAGE 40960
#define GP_SMEM (2 * GP_STAGE)          // 81,920 B

template<int MODE>
__global__ __launch_bounds__(256) void gemm_pipe(
    const __nv_bfloat16* __restrict__ Ahi, const __nv_bfloat16* __restrict__ Alo,
    const __nv_bfloat16* __restrict__ Bhi, const __nv_bfloat16* __restrict__ Blo,
    const float* __restrict__ bias,
    float* __restrict__ oF,
    __nv_bfloat16* __restrict__ okh, __nv_bfloat16* __restrict__ okl,
    __nv_bfloat16* __restrict__ oqh, __nv_bfloat16* __restrict__ oql,
    __nv_bfloat16* __restrict__ ovh, __nv_bfloat16* __restrict__ ovl)
{
    extern __shared__ __nv_bfloat16 smem[];
    const uint32_t sb0 = smem_u32(smem);
    const int tid  = threadIdx.x;
    const int lane = tid & 31;
    const int wid  = tid >> 5;
    const int wm   = wid >> 2;
    const int wn   = wid & 3;
    const int m0 = blockIdx.x * 128;
    const int n0 = blockIdx.y * 128;

    float acc[4][4][4] = {};

    const uint32_t a_row  = (uint32_t)(wm * 64 + (lane & 15));
    const uint32_t a_coff = (uint32_t)(((lane >> 4) << 3) * 2);
    const uint32_t b_row  = (uint32_t)(wn * 32 + (lane & 7) + ((lane & 16) >> 1));
    const uint32_t b_coff = (uint32_t)((lane & 8) * 2);

    const int lr0 = tid >> 2, lc0 = tid & 3;
    const int lr1 = (tid + 256) >> 2;

    auto load_chunk = [&](int kc, int st) {
        const uint32_t sbs = sb0 + st * GP_STAGE;
        const uint32_t so0 = (uint32_t)(lr0 * GP_LDS + lc0 * 8) * 2;
        const uint32_t so1 = (uint32_t)(lr1 * GP_LDS + lc0 * 8) * 2;
        size_t ga0 = (size_t)(m0 + lr0) * D_ + kc * 32 + lc0 * 8;
        size_t ga1 = (size_t)(m0 + lr1) * D_ + kc * 32 + lc0 * 8;
        size_t gb0 = (size_t)(n0 + lr0) * D_ + kc * 32 + lc0 * 8;
        size_t gb1 = (size_t)(n0 + lr1) * D_ + kc * 32 + lc0 * 8;
        CP16(sbs + GP_AH + so0, Ahi + ga0);
        CP16(sbs + GP_AH + so1, Ahi + ga1);
        CP16(sbs + GP_AL + so0, Alo + ga0);
        CP16(sbs + GP_AL + so1, Alo + ga1);
        CP16(sbs + GP_BH + so0, Bhi + gb0);
        CP16(sbs + GP_BH + so1, Bhi + gb1);
        CP16(sbs + GP_BL + so0, Blo + gb0);
        CP16(sbs + GP_BL + so1, Blo + gb1);
    };

    load_chunk(0, 0);
    CP_COMMIT();

    for (int kc = 0; kc < 32; kc++) {
        const int cur = kc & 1;
        if (kc + 1 < 32) {
            load_chunk(kc + 1, cur ^ 1);
            CP_COMMIT();
            CP_WAIT1();
        } else {
            CP_WAIT0();
        }
        __syncthreads();

        const uint32_t sbs = sb0 + cur * GP_STAGE;
        const uint32_t s_ah = sbs + GP_AH, s_al = sbs + GP_AL;
        const uint32_t s_bh = sbs + GP_BH, s_bl = sbs + GP_BL;

        #pragma unroll
        for (int kk = 0; kk < 2; kk++) {
            const uint32_t kb = (uint32_t)(kk * 16 * 2);
            uint32_t bhf[2][4], blf[2][4];
            #pragma unroll
            for (int g = 0; g < 2; g++) {
                uint32_t ba = (b_row + g * 16) * (GP_LDS * 2) + kb + b_coff;
                LDM4(bhf[g], s_bh + ba);
                LDM4(blf[g], s_bl + ba);
            }
            // mt-pairs: 8 independent accumulator tiles between any reuse
            #pragma unroll
            for (int mp = 0; mp < 2; mp++) {
                uint32_t ahf[2][4], alf[2][4];
                #pragma unroll
                for (int i = 0; i < 2; i++) {
                    uint32_t aa = (a_row + (mp * 2 + i) * 16) * (GP_LDS * 2) + kb + a_coff;
                    LDM4(ahf[i], s_ah + aa);
                    LDM4(alf[i], s_al + aa);
                }
                // term hh
                #pragma unroll
                for (int i = 0; i < 2; i++)
                    #pragma unroll
                    for (int nt = 0; nt < 4; nt++)
                        MMA_BF16(acc[mp*2+i][nt], ahf[i], bhf[nt>>1][(nt&1)*2], bhf[nt>>1][(nt&1)*2+1]);
                // term hl
                #pragma unroll
                for (int i = 0; i < 2; i++)
                    #pragma unroll
                    for (int nt = 0; nt < 4; nt++)
                        MMA_BF16(acc[mp*2+i][nt], ahf[i], blf[nt>>1][(nt&1)*2], blf[nt>>1][(nt&1)*2+1]);
                // term lh
                #pragma unroll
                for (int i = 0; i < 2; i++)
                    #pragma unroll
                    for (int nt = 0; nt < 4; nt++)
                        MMA_BF16(acc[mp*2+i][nt], alf[i], bhf[nt>>1][(nt&1)*2], bhf[nt>>1][(nt&1)*2+1]);
            }
        }
        __syncthreads();
    }

    const int row0 = wm * 64 + (lane >> 2);
    const int col0 = wn * 32 + (lane & 3) * 2;
    #pragma unroll
    for (int mt = 0; mt < 4; mt++) {
        #pragma unroll
        for (int nt = 0; nt < 4; nt++) {
            #pragma unroll
            for (int r = 0; r < 4; r++) {
                int m = m0 + row0 + mt * 16 + (r >> 1) * 8;
                int j = n0 + col0 + nt * 8 + (r & 1);
                float val = acc[mt][nt][r] + bias[j];
                if (MODE == 1) {
                    oF[(size_t)m * D_ + j] = val;
                } else {
                    int b = m >> 11, n = m & (N_ - 1);
                    int h = j / E3_, e = j % E3_;
                    __nv_bfloat16 vh, vl; bf_split(val, vh, vl);
                    if (e < DH_) {
                        size_t o = ((size_t)(b * H_ + h) * N_ + n) * DH_ + e;
                        okh[o] = vh; okl[o] = vl;
                    } else if (e < 2 * DH_) {
                        size_t o = ((size_t)(b * H_ + h) * N_ + n) * DH_ + (e - DH_);
                        oqh[o] = vh; oql[o] = vl;
                    } else {
                        size_t o = ((size_t)(b * H_ + h) * DH_ + (e - 2 * DH_)) * N_ + n;
                        ovh[o] = vh; ovl[o] = vl;
                    }
                }
            }
        }
    }
}

// ---------------------------------------------------------------------------
// scores_mma: 128x128 tiles, kt <= qt, single K=64 shot, term-major MMA issue.
// ---------------------------------------------------------------------------
#define SC_LDS 72
#define SC_TILE (128 * SC_LDS)
#define SC_AH 0
#define SC_AL (1 * SC_TILE)
#define SC_BH (2 * SC_TILE)
#define SC_BL (3 * SC_TILE)
#define SC_SMEM (4 * SC_TILE * 2)

__global__ __launch_bounds__(256) void scores_mma(
    const __nv_bfloat16* __restrict__ Qh, const __nv_bfloat16* __restrict__ Ql,
    const __nv_bfloat16* __restrict__ Kh, const __nv_bfloat16* __restrict__ Kl,
    float* __restrict__ attn)
{
    const int qt = blockIdx.x, kt = blockIdx.y, bh = blockIdx.z;
    if (kt > qt) return;

    extern __shared__ __nv_bfloat16 smem[];
    const int tid  = threadIdx.x;
    const int lane = tid & 31;
    const int wid  = tid >> 5;
    const int wm   = wid >> 2;
    const int wn   = wid & 3;

    const uint32_t s_ah = smem_u32(smem) + SC_AH * 2;
    const uint32_t s_al = smem_u32(smem) + SC_AL * 2;
    const uint32_t s_bh = smem_u32(smem) + SC_BH * 2;
    const uint32_t s_bl = smem_u32(smem) + SC_BL * 2;

    const __nv_bfloat16* qhb = Qh + ((size_t)bh * N_ + qt * 128) * DH_;
    const __nv_bfloat16* qlb = Ql + ((size_t)bh * N_ + qt * 128) * DH_;
    const __nv_bfloat16* khb = Kh + ((size_t)bh * N_ + kt * 128) * DH_;
    const __nv_bfloat16* klb = Kl + ((size_t)bh * N_ + kt * 128) * DH_;

    #pragma unroll
    for (int i = 0; i < 4; i++) {
        int u  = tid + i * 256;
        int r  = u >> 3, c8 = u & 7;
        int so = r * SC_LDS + c8 * 8;
        size_t g = (size_t)r * DH_ + c8 * 8;
        *(uint4*)(smem + SC_AH + so) = *(const uint4*)(qhb + g);
        *(uint4*)(smem + SC_AL + so) = *(const uint4*)(qlb + g);
        *(uint4*)(smem + SC_BH + so) = *(const uint4*)(khb + g);
        *(uint4*)(smem + SC_BL + so) = *(const uint4*)(klb + g);
    }
    __syncthreads();

    const uint32_t a_row  = (uint32_t)(wm * 64 + (lane & 15));
    const uint32_t a_coff = (uint32_t)(((lane >> 4) << 3) * 2);
    const uint32_t b_row  = (uint32_t)(wn * 32 + (lane & 7) + ((lane & 16) >> 1));
    const uint32_t b_coff = (uint32_t)((lane & 8) * 2);

    float acc[4][4][4] = {};
    #pragma unroll
    for (int kk = 0; kk < 4; kk++) {
        const uint32_t kb = (uint32_t)(kk * 16 * 2);
        uint32_t bhf[2][4], blf[2][4];
        #pragma unroll
        for (int g = 0; g < 2; g++) {
            uint32_t ba = (b_row + g * 16) * (SC_LDS * 2) + kb + b_coff;
            LDM4(bhf[g], s_bh + ba);
            LDM4(blf[g], s_bl + ba);
        }
        #pragma unroll
        for (int mp = 0; mp < 2; mp++) {
            uint32_t ahf[2][4], alf[2][4];
            #pragma unroll
            for (int i = 0; i < 2; i++) {
                uint32_t aa = (a_row + (mp * 2 + i) * 16) * (SC_LDS * 2) + kb + a_coff;
                LDM4(ahf[i], s_ah + aa);
                LDM4(alf[i], s_al + aa);
            }
            #pragma unroll
            for (int i = 0; i < 2; i++)
                #pragma unroll
                for (int nt = 0; nt < 4; nt++)
                    MMA_BF16(acc[mp*2+i][nt], ahf[i], bhf[nt>>1][(nt&1)*2], bhf[nt>>1][(nt&1)*2+1]);
            #pragma unroll
            for (int i = 0; i < 2; i++)
                #pragma unroll
                for (int nt = 0; nt < 4; nt++)
                    MMA_BF16(acc[mp*2+i][nt], ahf[i], blf[nt>>1][(nt&1)*2], blf[nt>>1][(nt&1)*2+1]);
            #pragma unroll
            for (int i = 0; i < 2; i++)
                #pragma unroll
                for (int nt = 0; nt < 4; nt++)
                    MMA_BF16(acc[mp*2+i][nt], alf[i], bhf[nt>>1][(nt&1)*2], bhf[nt>>1][(nt&1)*2+1]);
        }
    }

    float* abase = attn + (size_t)bh * N_ * N_;
    const int row0 = wm * 64 + (lane >> 2);
    const int col0 = wn * 32 + (lane & 3) * 2;
    #pragma unroll
    for (int mt = 0; mt < 4; mt++) {
        #pragma unroll
        for (int nt = 0; nt < 4; nt++) {
            #pragma unroll
            for (int r = 0; r < 4; r++) {
                int qi = qt * 128 + row0 + mt * 16 + (r >> 1) * 8;
                int ki = kt * 128 + col0 + nt * 8 + (r & 1);
                abase[(size_t)qi * N_ + ki] = acc[mt][nt][r] * 0.125f;
            }
        }
    }
}

// ---------------------------------------------------------------------------
// softmax2 (unchanged)
// ---------------------------------------------------------------------------
__global__ __launch_bounds__(256) void softmax2(
    float* __restrict__ attn,
    __nv_bfloat16* __restrict__ pbh, __nv_bfloat16* __restrict__ pbl)
{
    __shared__ float row[N_];
    __shared__ float red[256];

    const size_t r = blockIdx.x;
    const int qpos = blockIdx.x & (N_ - 1);
    const int kmax = ((qpos >> 7) + 1) << 7;
    float* s = attn + r * N_;
    __nv_bfloat16* ph = pbh + r * N_;
    __nv_bfloat16* pl = pbl + r * N_;
    const int tid = threadIdx.x;

    float m = -1e30f;
    for (int i = tid; i <= qpos; i += 256) {
        float v = s[i];
        row[i] = v;
        m = fmaxf(m, v);
    }
    red[tid] = m; __syncthreads();
    #pragma unroll
    for (int o = 128; o > 0; o >>= 1) {
        if (tid < o) red[tid] = fmaxf(red[tid], red[tid + o]);
        __syncthreads();
    }
    m = red[0]; __syncthreads();

    float sum = 0.f;
    for (int i = tid; i <= qpos; i += 256) {
        float e = __expf(row[i] - m);
        row[i] = e;
        sum += e;
    }
    red[tid] = sum; __syncthreads();
    #pragma unroll
    for (int o = 128; o > 0; o >>= 1) {
        if (tid < o) red[tid] += red[tid + o];
        __syncthreads();
    }
    const float inv = 1.0f / red[0];

    for (int i = tid; i < N_; i += 256) {
        float p = (i <= qpos) ? row[i] * inv : 0.f;
        s[i] = p;
        if (i < kmax) {
            __nv_bfloat16 h, l; bf_split(p, h, l);
            ph[i] = h; pl[i] = l;
        }
    }
}

// ---------------------------------------------------------------------------
// sa_pipe: sa = P @ V, 2-stage cp.async pipeline, K-chunks of 64.
// Term-major MMA issue over all 4 mt (8 independent tiles between reuse).
// ---------------------------------------------------------------------------
#define SP_LDS 72
#define SP_PH 0
#define SP_PL 18432
#define SP_VH 36864
#define SP_VL 46080
#define SP_STAGE 55296
#define SP_SMEM (2 * SP_STAGE)          // 110,592 B

__global__ __launch_bounds__(256) void sa_pipe(
    const __nv_bfloat16* __restrict__ Ph, const __nv_bfloat16* __restrict__ Pl,
    const __nv_bfloat16* __restrict__ Vth, const __nv_bfloat16* __restrict__ Vtl,
    __nv_bfloat16* __restrict__ sahi, __nv_bfloat16* __restrict__ salo)
{
    extern __shared__ __nv_bfloat16 smem[];
    const uint32_t sb0 = smem_u32(smem);
    const int bh = blockIdx.x;
    const int qt = (N_ / 128 - 1) - blockIdx.y;
    const int tid  = threadIdx.x;
    const int lane = tid & 31;
    const int wid  = tid >> 5;
    const int wm   = wid >> 2;
    const int wn   = wid & 3;

    const __nv_bfloat16* phb = Ph + ((size_t)bh * N_ + qt * 128) * N_;
    const __nv_bfloat16* plb = Pl + ((size_t)bh * N_ + qt * 128) * N_;
    const __nv_bfloat16* vhb = Vth + (size_t)bh * DH_ * N_;
    const __nv_bfloat16* vlb = Vtl + (size_t)bh * DH_ * N_;

    float acc[4][2][4] = {};

    const uint32_t a_row  = (uint32_t)(wm * 64 + (lane & 15));
    const uint32_t a_coff = (uint32_t)(((lane >> 4) << 3) * 2);
    const uint32_t b_row  = (uint32_t)(wn * 16 + (lane & 7) + ((lane & 16) >> 1));
    const uint32_t b_coff = (uint32_t)((lane & 8) * 2);

    const int lr = tid >> 3, lc = tid & 7;

    auto load_chunk = [&](int kc, int st) {
        const uint32_t sbs = sb0 + st * SP_STAGE;
        const int kofs = kc * 64 + lc * 8;
        #pragma unroll
        for (int i = 0; i < 4; i++) {
            int r = lr + i * 32;
            uint32_t so = (uint32_t)(r * SP_LDS + lc * 8) * 2;
            size_t g = (size_t)r * N_ + kofs;
            CP16(sbs + SP_PH + so, phb + g);
            CP16(sbs + SP_PL + so, plb + g);
        }
        #pragma unroll
        for (int i = 0; i < 2; i++) {
            int r = lr + i * 32;
            uint32_t so = (uint32_t)(r * SP_LDS + lc * 8) * 2;
            size_t g = (size_t)r * N_ + kofs;
            CP16(sbs + SP_VH + so, vhb + g);
            CP16(sbs + SP_VL + so, vlb + g);
        }
    };

    const int nchunks = (qt + 1) * 2;
    load_chunk(0, 0);
    CP_COMMIT();

    for (int kc = 0; kc < nchunks; kc++) {
        const int cur = kc & 1;
        if (kc + 1 < nchunks) {
            load_chunk(kc + 1, cur ^ 1);
            CP_COMMIT();
            CP_WAIT1();
        } else {
            CP_WAIT0();
        }
        __syncthreads();

        const uint32_t sbs = sb0 + cur * SP_STAGE;
        const uint32_t s_ph = sbs + SP_PH, s_pl = sbs + SP_PL;
        const uint32_t s_vh = sbs + SP_VH, s_vl = sbs + SP_VL;

        #pragma unroll
        for (int kk = 0; kk < 4; kk++) {
            const uint32_t kb = (uint32_t)(kk * 16 * 2);
            uint32_t bhf[4], blf[4];
            uint32_t ba = b_row * (SP_LDS * 2) + kb + b_coff;
            LDM4(bhf, s_vh + ba);
            LDM4(blf, s_vl + ba);
            uint32_t ahf[4][4], alf[4][4];
            #pragma unroll
            for (int mt = 0; mt < 4; mt++) {
                uint32_t aa = (a_row + mt * 16) * (SP_LDS * 2) + kb + a_coff;
                LDM4(ahf[mt], s_ph + aa);
                LDM4(alf[mt], s_pl + aa);
            }
            #pragma unroll
            for (int mt = 0; mt < 4; mt++)
                #pragma unroll
                for (int nt = 0; nt < 2; nt++)
                    MMA_BF16(acc[mt][nt], ahf[mt], bhf[nt*2], bhf[nt*2+1]);
            #pragma unroll
            for (int mt = 0; mt < 4; mt++)
                #pragma unroll
                for (int nt = 0; nt < 2; nt++)
                    MMA_BF16(acc[mt][nt], ahf[mt], blf[nt*2], blf[nt*2+1]);
            #pragma unroll
            for (int mt = 0; mt < 4; mt++)
                #pragma unroll
                for (int nt = 0; nt < 2; nt++)
                    MMA_BF16(acc[mt][nt], alf[mt], bhf[nt*2], bhf[nt*2+1]);
        }
        __syncthreads();
    }

    const int b = bh >> 4, h = bh & 15;
    const int row0 = wm * 64 + (lane >> 2);
    const int col0 = wn * 16 + (lane & 3) * 2;
    #pragma unroll
    for (int mt = 0; mt < 4; mt++) {
        #pragma unroll
        for (int nt = 0; nt < 2; nt++) {
            #pragma unroll
            for (int r = 0; r < 4; r++) {
                int n  = qt * 128 + row0 + mt * 16 + (r >> 1) * 8;
                int dh = col0 + nt * 8 + (r & 1);
                size_t o = ((size_t)b * N_ + n) * D_ + h * DH_ + dh;
                __nv_bfloat16 vh, vl; bf_split(acc[mt][nt][r], vh, vl);
                sahi[o] = vh; salo[o] = vl;
            }
        }
    }
}

// ---------------------------------------------------------------------------
extern "C" void kernel_launch(void* const* d_in, const int* in_sizes, int n_in,
                              void* d_out, int out_size)
{
    const float* x     = (const float*)d_in[0];
    const float* Wqkv  = (const float*)d_in[1];
    const float* bqkv  = (const float*)d_in[2];
    const float* Wproj = (const float*)d_in[3];
    const float* bproj = (const float*)d_in[4];
    float* out = (float*)d_out;

    const size_t OUT_ELEMS  = (size_t)B_ * N_ * D_;
    const size_t ATTN_ELEMS = (size_t)B_ * H_ * N_ * N_;

    float* attnp;
    cudaGetSymbolAddress((void**)&attnp, g_attn);
    if ((size_t)out_size >= OUT_ELEMS + ATTN_ELEMS)
        attnp = out + OUT_ELEMS;

    __nv_bfloat16 *xhi, *xlo, *wqhi, *wqlo, *wphi, *wplo, *sahi, *salo;
    __nv_bfloat16 *qh, *ql, *kh, *kl, *vth, *vtl, *pbh, *pbl;
    cudaGetSymbolAddress((void**)&xhi,  g_xhi);
    cudaGetSymbolAddress((void**)&xlo,  g_xlo);
    cudaGetSymbolAddress((void**)&wqhi, g_wqhi);
    cudaGetSymbolAddress((void**)&wqlo, g_wqlo);
    cudaGetSymbolAddress((void**)&wphi, g_wphi);
    cudaGetSymbolAddress((void**)&wplo, g_wplo);
    cudaGetSymbolAddress((void**)&sahi, g_sahi);
    cudaGetSymbolAddress((void**)&salo, g_salo);
    cudaGetSymbolAddress((void**)&qh,   g_qh);
    cudaGetSymbolAddress((void**)&ql,   g_ql);
    cudaGetSymbolAddress((void**)&kh,   g_kh);
    cudaGetSymbolAddress((void**)&kl,   g_kl);
    cudaGetSymbolAddress((void**)&vth,  g_vth);
    cudaGetSymbolAddress((void**)&vtl,  g_vtl);
    cudaGetSymbolAddress((void**)&pbh,  g_pbh);
    cudaGetSymbolAddress((void**)&pbl,  g_pbl);

    cudaFuncSetAttribute(gemm_pipe<0>, cudaFuncAttributeMaxDynamicSharedMemorySize, GP_SMEM);
    cudaFuncSetAttribute(gemm_pipe<1>, cudaFuncAttributeMaxDynamicSharedMemorySize, GP_SMEM);
    cudaFuncSetAttribute(scores_mma,   cudaFuncAttributeMaxDynamicSharedMemorySize, SC_SMEM);
    cudaFuncSetAttribute(sa_pipe,      cudaFuncAttributeMaxDynamicSharedMemorySize, SP_SMEM);

    split_kernel<<<(M_ * D_ + 255) / 256, 256>>>(x, xhi, xlo, M_ * D_);
    split_wqkv_kernel<<<(J3_ * D_ + 255) / 256, 256>>>(Wqkv, wqhi, wqlo);
    split_kernel<<<(D_ * D_ + 255) / 256, 256>>>(Wproj, wphi, wplo, D_ * D_);

    gemm_pipe<0><<<dim3(M_ / 128, J3_ / 128), 256, GP_SMEM>>>(
        xhi, xlo, wqhi, wqlo, bqkv, nullptr, kh, kl, qh, ql, vth, vtl);

    scores_mma<<<dim3(N_ / 128, N_ / 128, B_ * H_), 256, SC_SMEM>>>(
        qh, ql, kh, kl, attnp);

    softmax2<<<B_ * H_ * N_, 256>>>(attnp, pbh, pbl);

    sa_pipe<<<dim3(B_ * H_, N_ / 128), 256, SP_SMEM>>>(
        pbh, pbl, vth, vtl, sahi, salo);

    gemm_pipe<1><<<dim3(M_ / 128, D_ / 128), 256, GP_SMEM>>>(
        sahi, salo, wphi, wplo, bproj, out,
        nullptr, nullptr, nullptr, nullptr, nullptr, nullptr);
}

// round 7
// speedup vs baseline: 1.1522x; 1.1522x over previous
#include <cuda_runtime.h>
#include <cuda_bf16.h>
#include <math.h>
#include <stdint.h>

// Problem constants
#define B_  2
#define N_  2048
#define D_  1024
#define H_  16
#define DH_ 64
#define E3_ 192
#define J3_ 3072
#define M_  4096

// ---------------------------------------------------------------------------
// Scratch (device globals)
// ---------------------------------------------------------------------------
__device__ float g_attn[(size_t)B_*H_*N_*N_];

__device__ __nv_bfloat16 g_xhi [(size_t)M_*D_];
__device__ __nv_bfloat16 g_xlo [(size_t)M_*D_];
__device__ __nv_bfloat16 g_wqhi[(size_t)J3_*D_];
__device__ __nv_bfloat16 g_wqlo[(size_t)J3_*D_];
__device__ __nv_bfloat16 g_wphi[(size_t)D_*D_];
__device__ __nv_bfloat16 g_wplo[(size_t)D_*D_];
__device__ __nv_bfloat16 g_sahi[(size_t)M_*D_];
__device__ __nv_bfloat16 g_salo[(size_t)M_*D_];

__device__ __nv_bfloat16 g_qh[(size_t)B_*H_*N_*DH_];
__device__ __nv_bfloat16 g_ql[(size_t)B_*H_*N_*DH_];
__device__ __nv_bfloat16 g_kh[(size_t)B_*H_*N_*DH_];
__device__ __nv_bfloat16 g_kl[(size_t)B_*H_*N_*DH_];
__device__ __nv_bfloat16 g_vth[(size_t)B_*H_*DH_*N_];
__device__ __nv_bfloat16 g_vtl[(size_t)B_*H_*DH_*N_];

__device__ __nv_bfloat16 g_pbh[(size_t)B_*H_*N_*N_];
__device__ __nv_bfloat16 g_pbl[(size_t)B_*H_*N_*N_];

// ---------------------------------------------------------------------------
// Helpers
// ---------------------------------------------------------------------------
__device__ __forceinline__ uint32_t smem_u32(const void* p) {
    uint32_t a;
    asm("{ .reg .u64 t; cvta.to.shared.u64 t, %1; cvt.u32.u64 %0, t; }"
        : "=r"(a) : "l"(p));
    return a;
}

#define LDM4(r, addr)                                                         \
    asm volatile("ldmatrix.sync.aligned.m8n8.x4.shared.b16 {%0,%1,%2,%3}, [%4];" \
        : "=r"((r)[0]), "=r"((r)[1]), "=r"((r)[2]), "=r"((r)[3])              \
        : "r"(addr))

#define MMA_BF16(c, a, b0, b1)                                                \
    asm volatile("mma.sync.aligned.m16n8k16.row.col.f32.bf16.bf16.f32 "       \
        "{%0,%1,%2,%3}, {%4,%5,%6,%7}, {%8,%9}, {%0,%1,%2,%3};"               \
        : "+f"((c)[0]), "+f"((c)[1]), "+f"((c)[2]), "+f"((c)[3])              \
        : "r"((a)[0]), "r"((a)[1]), "r"((a)[2]), "r"((a)[3]), "r"(b0), "r"(b1))

#define CP16(dst, src)                                                        \
    asm volatile("cp.async.cg.shared.global [%0], [%1], 16;"                  \
        :: "r"(dst), "l"(src))
#define CP_COMMIT() asm volatile("cp.async.commit_group;" ::: "memory")
#define CP_WAIT0()  asm volatile("cp.async.wait_group 0;" ::: "memory")

__device__ __forceinline__ void bf_split(float v, __nv_bfloat16& h, __nv_bfloat16& l) {
    h = __float2bfloat16(v);
    l = __float2bfloat16(v - __bfloat162float(h));
}

__device__ __forceinline__ uint32_t bf_pack(__nv_bfloat16 a, __nv_bfloat16 b) {
    __nv_bfloat162 t(a, b);
    return *reinterpret_cast<uint32_t*>(&t);
}

// ---------------------------------------------------------------------------
// Fused split kernel: x, Wqkv (with transpose), Wproj in one launch.
// ---------------------------------------------------------------------------
#define XBLK (M_ * D_ / 256)          // 16384
#define WQBLK (J3_ * D_ / 256)        // 12288
#define WPBLK (D_ * D_ / 256)         // 4096

__global__ __launch_bounds__(256) void split_all(
    const float* __restrict__ x, const float* __restrict__ Wqkv,
    const float* __restrict__ Wproj,
    __nv_bfloat16* __restrict__ xhi, __nv_bfloat16* __restrict__ xlo,
    __nv_bfloat16* __restrict__ wqhi, __nv_bfloat16* __restrict__ wqlo,
    __nv_bfloat16* __restrict__ wphi, __nv_bfloat16* __restrict__ wplo)
{
    int blk = blockIdx.x;
    if (blk < XBLK) {
        int i = blk * 256 + threadIdx.x;
        float v = x[i];
        __nv_bfloat16 h, l; bf_split(v, h, l);
        xhi[i] = h; xlo[i] = l;
    } else if (blk < XBLK + WQBLK) {
        int idx = (blk - XBLK) * 256 + threadIdx.x;
        int j = idx >> 10, d = idx & 1023;
        int h = j / E3_, e = j % E3_;
        float v = Wqkv[((size_t)h * D_ + d) * E3_ + e];
        __nv_bfloat16 vh, vl; bf_split(v, vh, vl);
        wqhi[idx] = vh; wqlo[idx] = vl;
    } else {
        int i = (blk - XBLK - WQBLK) * 256 + threadIdx.x;
        float v = Wproj[i];
        __nv_bfloat16 h, l; bf_split(v, h, l);
        wphi[i] = h; wplo[i] = l;
    }
}

// ---------------------------------------------------------------------------
// gemm_pipe: 2-stage cp.async pipelined split-bf16 GEMM, K=1024, chunk 32.
// SINGLE __syncthreads per chunk: wait0 -> sync -> issue next loads -> compute.
// (sync provides both cp.async visibility and stage-reuse safety)
// ---------------------------------------------------------------------------
#define GP_LDS 40
#define GP_AH 0
#define GP_AL 10240
#define GP_BH 20480
#define GP_BL 30720
#define GP_STAGE 40960
#define GP_SMEM (2 * GP_STAGE)          // 81,920 B

template<int MODE>
__global__ __launch_bounds__(256) void gemm_pipe(
    const __nv_bfloat16* __restrict__ Ahi, const __nv_bfloat16* __restrict__ Alo,
    const __nv_bfloat16* __restrict__ Bhi, const __nv_bfloat16* __restrict__ Blo,
    const float* __restrict__ bias,
    float* __restrict__ oF,
    __nv_bfloat16* __restrict__ okh, __nv_bfloat16* __restrict__ okl,
    __nv_bfloat16* __restrict__ oqh, __nv_bfloat16* __restrict__ oql,
    __nv_bfloat16* __restrict__ ovh, __nv_bfloat16* __restrict__ ovl)
{
    extern __shared__ __nv_bfloat16 smem[];
    const uint32_t sb0 = smem_u32(smem);
    const int tid  = threadIdx.x;
    const int lane = tid & 31;
    const int wid  = tid >> 5;
    const int wm   = wid >> 2;
    const int wn   = wid & 3;
    const int m0 = blockIdx.x * 128;
    const int n0 = blockIdx.y * 128;

    float acc[4][4][4] = {};

    const uint32_t a_row  = (uint32_t)(wm * 64 + (lane & 15));
    const uint32_t a_coff = (uint32_t)(((lane >> 4) << 3) * 2);
    const uint32_t b_row  = (uint32_t)(wn * 32 + (lane & 7) + ((lane & 16) >> 1));
    const uint32_t b_coff = (uint32_t)((lane & 8) * 2);

    const int lr0 = tid >> 2, lc0 = tid & 3;
    const int lr1 = (tid + 256) >> 2;

    auto load_chunk = [&](int kc, int st) {
        const uint32_t sbs = sb0 + st * GP_STAGE;
        const uint32_t so0 = (uint32_t)(lr0 * GP_LDS + lc0 * 8) * 2;
        const uint32_t so1 = (uint32_t)(lr1 * GP_LDS + lc0 * 8) * 2;
        size_t ga0 = (size_t)(m0 + lr0) * D_ + kc * 32 + lc0 * 8;
        size_t ga1 = (size_t)(m0 + lr1) * D_ + kc * 32 + lc0 * 8;
        size_t gb0 = (size_t)(n0 + lr0) * D_ + kc * 32 + lc0 * 8;
        size_t gb1 = (size_t)(n0 + lr1) * D_ + kc * 32 + lc0 * 8;
        CP16(sbs + GP_AH + so0, Ahi + ga0);
        CP16(sbs + GP_AH + so1, Ahi + ga1);
        CP16(sbs + GP_AL + so0, Alo + ga0);
        CP16(sbs + GP_AL + so1, Alo + ga1);
        CP16(sbs + GP_BH + so0, Bhi + gb0);
        CP16(sbs + GP_BH + so1, Bhi + gb1);
        CP16(sbs + GP_BL + so0, Blo + gb0);
        CP16(sbs + GP_BL + so1, Blo + gb1);
    };

    load_chunk(0, 0);
    CP_COMMIT();

    for (int kc = 0; kc < 32; kc++) {
        const int cur = kc & 1;
        CP_WAIT0();           // chunk kc data complete (this thread)
        __syncthreads();      // visibility + all warps done with stage cur (from kc-2)
        if (kc + 1 < 32) {
            load_chunk(kc + 1, cur ^ 1);
            CP_COMMIT();
        }

        const uint32_t sbs = sb0 + cur * GP_STAGE;
        const uint32_t s_ah = sbs + GP_AH, s_al = sbs + GP_AL;
        const uint32_t s_bh = sbs + GP_BH, s_bl = sbs + GP_BL;

        #pragma unroll
        for (int kk = 0; kk < 2; kk++) {
            const uint32_t kb = (uint32_t)(kk * 16 * 2);
            uint32_t bhf[2][4], blf[2][4];
            #pragma unroll
            for (int g = 0; g < 2; g++) {
                uint32_t ba = (b_row + g * 16) * (GP_LDS * 2) + kb + b_coff;
                LDM4(bhf[g], s_bh + ba);
                LDM4(blf[g], s_bl + ba);
            }
            #pragma unroll
            for (int mp = 0; mp < 2; mp++) {
                uint32_t ahf[2][4], alf[2][4];
                #pragma unroll
                for (int i = 0; i < 2; i++) {
                    uint32_t aa = (a_row + (mp * 2 + i) * 16) * (GP_LDS * 2) + kb + a_coff;
                    LDM4(ahf[i], s_ah + aa);
                    LDM4(alf[i], s_al + aa);
                }
                #pragma unroll
                for (int i = 0; i < 2; i++)
                    #pragma unroll
                    for (int nt = 0; nt < 4; nt++)
                        MMA_BF16(acc[mp*2+i][nt], ahf[i], bhf[nt>>1][(nt&1)*2], bhf[nt>>1][(nt&1)*2+1]);
                #pragma unroll
                for (int i = 0; i < 2; i++)
                    #pragma unroll
                    for (int nt = 0; nt < 4; nt++)
                        MMA_BF16(acc[mp*2+i][nt], ahf[i], blf[nt>>1][(nt&1)*2], blf[nt>>1][(nt&1)*2+1]);
                #pragma unroll
                for (int i = 0; i < 2; i++)
                    #pragma unroll
                    for (int nt = 0; nt < 4; nt++)
                        MMA_BF16(acc[mp*2+i][nt], alf[i], bhf[nt>>1][(nt&1)*2], bhf[nt>>1][(nt&1)*2+1]);
            }
        }
    }

    const int row0 = wm * 64 + (lane >> 2);
    const int col0 = wn * 32 + (lane & 3) * 2;
    #pragma unroll
    for (int mt = 0; mt < 4; mt++) {
        #pragma unroll
        for (int nt = 0; nt < 4; nt++) {
            #pragma unroll
            for (int r = 0; r < 4; r++) {
                int m = m0 + row0 + mt * 16 + (r >> 1) * 8;
                int j = n0 + col0 + nt * 8 + (r & 1);
                float val = acc[mt][nt][r] + bias[j];
                if (MODE == 1) {
                    oF[(size_t)m * D_ + j] = val;
                } else {
                    int b = m >> 11, n = m & (N_ - 1);
                    int h = j / E3_, e = j % E3_;
                    __nv_bfloat16 vh, vl; bf_split(val, vh, vl);
                    if (e < DH_) {
                        size_t o = ((size_t)(b * H_ + h) * N_ + n) * DH_ + e;
                        okh[o] = vh; okl[o] = vl;
                    } else if (e < 2 * DH_) {
                        size_t o = ((size_t)(b * H_ + h) * N_ + n) * DH_ + (e - DH_);
                        oqh[o] = vh; oql[o] = vl;
                    } else {
                        size_t o = ((size_t)(b * H_ + h) * DH_ + (e - 2 * DH_)) * N_ + n;
                        ovh[o] = vh; ovl[o] = vl;
                    }
                }
            }
        }
    }
}

// ---------------------------------------------------------------------------
// scores_mma: 128x128 tiles, kt <= qt, single K=64 shot (cp.async fill).
// ---------------------------------------------------------------------------
#define SC_LDS 72
#define SC_TILE (128 * SC_LDS)
#define SC_AH 0
#define SC_AL (1 * SC_TILE)
#define SC_BH (2 * SC_TILE)
#define SC_BL (3 * SC_TILE)
#define SC_SMEM (4 * SC_TILE * 2)

__global__ __launch_bounds__(256) void scores_mma(
    const __nv_bfloat16* __restrict__ Qh, const __nv_bfloat16* __restrict__ Ql,
    const __nv_bfloat16* __restrict__ Kh, const __nv_bfloat16* __restrict__ Kl,
    float* __restrict__ attn)
{
    const int qt = blockIdx.x, kt = blockIdx.y, bh = blockIdx.z;
    if (kt > qt) return;

    extern __shared__ __nv_bfloat16 smem[];
    const uint32_t sb0 = smem_u32(smem);
    const int tid  = threadIdx.x;
    const int lane = tid & 31;
    const int wid  = tid >> 5;
    const int wm   = wid >> 2;
    const int wn   = wid & 3;

    const uint32_t s_ah = sb0 + SC_AH * 2;
    const uint32_t s_al = sb0 + SC_AL * 2;
    const uint32_t s_bh = sb0 + SC_BH * 2;
    const uint32_t s_bl = sb0 + SC_BL * 2;

    const __nv_bfloat16* qhb = Qh + ((size_t)bh * N_ + qt * 128) * DH_;
    const __nv_bfloat16* qlb = Ql + ((size_t)bh * N_ + qt * 128) * DH_;
    const __nv_bfloat16* khb = Kh + ((size_t)bh * N_ + kt * 128) * DH_;
    const __nv_bfloat16* klb = Kl + ((size_t)bh * N_ + kt * 128) * DH_;

    #pragma unroll
    for (int i = 0; i < 4; i++) {
        int u  = tid + i * 256;
        int r  = u >> 3, c8 = u & 7;
        uint32_t so = (uint32_t)(r * SC_LDS + c8 * 8) * 2;
        size_t g = (size_t)r * DH_ + c8 * 8;
        CP16(s_ah + so, qhb + g);
        CP16(s_al + so, qlb + g);
        CP16(s_bh + so, khb + g);
        CP16(s_bl + so, klb + g);
    }
    CP_COMMIT();
    CP_WAIT0();
    __syncthreads();

    const uint32_t a_row  = (uint32_t)(wm * 64 + (lane & 15));
    const uint32_t a_coff = (uint32_t)(((lane >> 4) << 3) * 2);
    const uint32_t b_row  = (uint32_t)(wn * 32 + (lane & 7) + ((lane & 16) >> 1));
    const uint32_t b_coff = (uint32_t)((lane & 8) * 2);

    float acc[4][4][4] = {};
    #pragma unroll
    for (int kk = 0; kk < 4; kk++) {
        const uint32_t kb = (uint32_t)(kk * 16 * 2);
        uint32_t bhf[2][4], blf[2][4];
        #pragma unroll
        for (int g = 0; g < 2; g++) {
            uint32_t ba = (b_row + g * 16) * (SC_LDS * 2) + kb + b_coff;
            LDM4(bhf[g], s_bh + ba);
            LDM4(blf[g], s_bl + ba);
        }
        #pragma unroll
        for (int mp = 0; mp < 2; mp++) {
            uint32_t ahf[2][4], alf[2][4];
            #pragma unroll
            for (int i = 0; i < 2; i++) {
                uint32_t aa = (a_row + (mp * 2 + i) * 16) * (SC_LDS * 2) + kb + a_coff;
                LDM4(ahf[i], s_ah + aa);
                LDM4(alf[i], s_al + aa);
            }
            #pragma unroll
            for (int i = 0; i < 2; i++)
                #pragma unroll
                for (int nt = 0; nt < 4; nt++)
                    MMA_BF16(acc[mp*2+i][nt], ahf[i], bhf[nt>>1][(nt&1)*2], bhf[nt>>1][(nt&1)*2+1]);
            #pragma unroll
            for (int i = 0; i < 2; i++)
                #pragma unroll
                for (int nt = 0; nt < 4; nt++)
                    MMA_BF16(acc[mp*2+i][nt], ahf[i], blf[nt>>1][(nt&1)*2], blf[nt>>1][(nt&1)*2+1]);
            #pragma unroll
            for (int i = 0; i < 2; i++)
                #pragma unroll
                for (int nt = 0; nt < 4; nt++)
                    MMA_BF16(acc[mp*2+i][nt], alf[i], bhf[nt>>1][(nt&1)*2], bhf[nt>>1][(nt&1)*2+1]);
        }
    }

    float* abase = attn + (size_t)bh * N_ * N_;
    const int row0 = wm * 64 + (lane >> 2);
    const int col0 = wn * 32 + (lane & 3) * 2;
    #pragma unroll
    for (int mt = 0; mt < 4; mt++) {
        #pragma unroll
        for (int nt = 0; nt < 4; nt++) {
            #pragma unroll
            for (int r = 0; r < 4; r++) {
                int qi = qt * 128 + row0 + mt * 16 + (r >> 1) * 8;
                int ki = kt * 128 + col0 + nt * 8 + (r & 1);
                abase[(size_t)qi * N_ + ki] = acc[mt][nt][r] * 0.125f;
            }
        }
    }
}

// ---------------------------------------------------------------------------
// softmax2: vectorized row softmax. Max is taken over the full 128-aligned
// region [0,kmax) — mathematically invariant (softmax shift) since the
// diagonal tile's upper part holds real finite scores. Sum/outputs masked.
// ---------------------------------------------------------------------------
__global__ __launch_bounds__(256) void softmax2(
    float* __restrict__ attn,
    __nv_bfloat16* __restrict__ pbh, __nv_bfloat16* __restrict__ pbl)
{
    __shared__ float row[N_];
    __shared__ float redm[8];
    __shared__ float reds[8];

    const size_t r = blockIdx.x;
    const int qpos = blockIdx.x & (N_ - 1);
    const int kmax = ((qpos >> 7) + 1) << 7;
    float* s = attn + r * N_;
    __nv_bfloat16* ph = pbh + r * N_;
    __nv_bfloat16* pl = pbl + r * N_;
    const int tid = threadIdx.x;
    const int lane = tid & 31, wrp = tid >> 5;

    // pass 1: cache + max (over full aligned region; shift-invariant)
    float m = -1e30f;
    for (int i = tid * 4; i < kmax; i += 1024) {
        float4 v = *(const float4*)(s + i);
        *(float4*)(row + i) = v;
        m = fmaxf(m, fmaxf(fmaxf(v.x, v.y), fmaxf(v.z, v.w)));
    }
    #pragma unroll
    for (int o = 16; o > 0; o >>= 1) m = fmaxf(m, __shfl_xor_sync(~0u, m, o));
    if (lane == 0) redm[wrp] = m;
    __syncthreads();
    m = fmaxf(fmaxf(fmaxf(redm[0], redm[1]), fmaxf(redm[2], redm[3])),
              fmaxf(fmaxf(redm[4], redm[5]), fmaxf(redm[6], redm[7])));

    // pass 2: exp + masked sum
    float sum = 0.f;
    for (int i = tid * 4; i < kmax; i += 1024) {
        float4 v = *(const float4*)(row + i);
        float4 e;
        e.x = __expf(v.x - m); e.y = __expf(v.y - m);
        e.z = __expf(v.z - m); e.w = __expf(v.w - m);
        *(float4*)(row + i) = e;
        sum += (i + 0 <= qpos ? e.x : 0.f) + (i + 1 <= qpos ? e.y : 0.f)
             + (i + 2 <= qpos ? e.z : 0.f) + (i + 3 <= qpos ? e.w : 0.f);
    }
    #pragma unroll
    for (int o = 16; o > 0; o >>= 1) sum += __shfl_xor_sync(~0u, sum, o);
    if (lane == 0) reds[wrp] = sum;
    __syncthreads();
    const float inv = 1.0f / (reds[0] + reds[1] + reds[2] + reds[3] +
                              reds[4] + reds[5] + reds[6] + reds[7]);

    // pass 3: masked normalized outputs (fp32 + bf16 hi/lo packed)
    for (int i = tid * 4; i < kmax; i += 1024) {
        float4 e = *(const float4*)(row + i);
        float4 p;
        p.x = (i + 0 <= qpos) ? e.x * inv : 0.f;
        p.y = (i + 1 <= qpos) ? e.y * inv : 0.f;
        p.z = (i + 2 <= qpos) ? e.z * inv : 0.f;
        p.w = (i + 3 <= qpos) ? e.w * inv : 0.f;
        *(float4*)(s + i) = p;
        __nv_bfloat16 h0, l0, h1, l1, h2, l2, h3, l3;
        bf_split(p.x, h0, l0); bf_split(p.y, h1, l1);
        bf_split(p.z, h2, l2); bf_split(p.w, h3, l3);
        uint2 uh = make_uint2(bf_pack(h0, h1), bf_pack(h2, h3));
        uint2 ul = make_uint2(bf_pack(l0, l1), bf_pack(l2, l3));
        *(uint2*)(ph + i) = uh;
        *(uint2*)(pl + i) = ul;
    }
    const float4 z4 = make_float4(0.f, 0.f, 0.f, 0.f);
    for (int i = kmax + tid * 4; i < N_; i += 1024)
        *(float4*)(s + i) = z4;
}

// ---------------------------------------------------------------------------
// sa_pipe: sa = P @ V, 2-stage cp.async, single sync per chunk.
// ---------------------------------------------------------------------------
#define SP_LDS 72
#define SP_PH 0
#define SP_PL 18432
#define SP_VH 36864
#define SP_VL 46080
#define SP_STAGE 55296
#define SP_SMEM (2 * SP_STAGE)          // 110,592 B

__global__ __launch_bounds__(256) void sa_pipe(
    const __nv_bfloat16* __restrict__ Ph, const __nv_bfloat16* __restrict__ Pl,
    const __nv_bfloat16* __restrict__ Vth, const __nv_bfloat16* __restrict__ Vtl,
    __nv_bfloat16* __restrict__ sahi, __nv_bfloat16* __restrict__ salo)
{
    extern __shared__ __nv_bfloat16 smem[];
    const uint32_t sb0 = smem_u32(smem);
    const int bh = blockIdx.x;
    const int qt = (N_ / 128 - 1) - blockIdx.y;
    const int tid  = threadIdx.x;
    const int lane = tid & 31;
    const int wid  = tid >> 5;
    const int wm   = wid >> 2;
    const int wn   = wid & 3;

    const __nv_bfloat16* phb = Ph + ((size_t)bh * N_ + qt * 128) * N_;
    const __nv_bfloat16* plb = Pl + ((size_t)bh * N_ + qt * 128) * N_;
    const __nv_bfloat16* vhb = Vth + (size_t)bh * DH_ * N_;
    const __nv_bfloat16* vlb = Vtl + (size_t)bh * DH_ * N_;

    float acc[4][2][4] = {};

    const uint32_t a_row  = (uint32_t)(wm * 64 + (lane & 15));
    const uint32_t a_coff = (uint32_t)(((lane >> 4) << 3) * 2);
    const uint32_t b_row  = (uint32_t)(wn * 16 + (lane & 7) + ((lane & 16) >> 1));
    const uint32_t b_coff = (uint32_t)((lane & 8) * 2);

    const int lr = tid >> 3, lc = tid & 7;

    auto load_chunk = [&](int kc, int st) {
        const uint32_t sbs = sb0 + st * SP_STAGE;
        const int kofs = kc * 64 + lc * 8;
        #pragma unroll
        for (int i = 0; i < 4; i++) {
            int r = lr + i * 32;
            uint32_t so = (uint32_t)(r * SP_LDS + lc * 8) * 2;
            size_t g = (size_t)r * N_ + kofs;
            CP16(sbs + SP_PH + so, phb + g);
            CP16(sbs + SP_PL + so, plb + g);
        }
        #pragma unroll
        for (int i = 0; i < 2; i++) {
            int r = lr + i * 32;
            uint32_t so = (uint32_t)(r * SP_LDS + lc * 8) * 2;
            size_t g = (size_t)r * N_ + kofs;
            CP16(sbs + SP_VH + so, vhb + g);
            CP16(sbs + SP_VL + so, vlb + g);
        }
    };

    const int nchunks = (qt + 1) * 2;
    load_chunk(0, 0);
    CP_COMMIT();

    for (int kc = 0; kc < nchunks; kc++) {
        const int cur = kc & 1;
        CP_WAIT0();
        __syncthreads();
        if (kc + 1 < nchunks) {
            load_chunk(kc + 1, cur ^ 1);
            CP_COMMIT();
        }

        const uint32_t sbs = sb0 + cur * SP_STAGE;
        const uint32_t s_ph = sbs + SP_PH, s_pl = sbs + SP_PL;
        const uint32_t s_vh = sbs + SP_VH, s_vl = sbs + SP_VL;

        #pragma unroll
        for (int kk = 0; kk < 4; kk++) {
            const uint32_t kb = (uint32_t)(kk * 16 * 2);
            uint32_t bhf[4], blf[4];
            uint32_t ba = b_row * (SP_LDS * 2) + kb + b_coff;
            LDM4(bhf, s_vh + ba);
            LDM4(blf, s_vl + ba);
            uint32_t ahf[4][4], alf[4][4];
            #pragma unroll
            for (int mt = 0; mt < 4; mt++) {
                uint32_t aa = (a_row + mt * 16) * (SP_LDS * 2) + kb + a_coff;
                LDM4(ahf[mt], s_ph + aa);
                LDM4(alf[mt], s_pl + aa);
            }
            #pragma unroll
            for (int mt = 0; mt < 4; mt++)
                #pragma unroll
                for (int nt = 0; nt < 2; nt++)
                    MMA_BF16(acc[mt][nt], ahf[mt], bhf[nt*2], bhf[nt*2+1]);
            #pragma unroll
            for (int mt = 0; mt < 4; mt++)
                #pragma unroll
                for (int nt = 0; nt < 2; nt++)
                    MMA_BF16(acc[mt][nt], ahf[mt], blf[nt*2], blf[nt*2+1]);
            #pragma unroll
            for (int mt = 0; mt < 4; mt++)
                #pragma unroll
                for (int nt = 0; nt < 2; nt++)
                    MMA_BF16(acc[mt][nt], alf[mt], bhf[nt*2], bhf[nt*2+1]);
        }
    }

    const int b = bh >> 4, h = bh & 15;
    const int row0 = wm * 64 + (lane >> 2);
    const int col0 = wn * 16 + (lane & 3) * 2;
    #pragma unroll
    for (int mt = 0; mt < 4; mt++) {
        #pragma unroll
        for (int nt = 0; nt < 2; nt++) {
            #pragma unroll
            for (int r = 0; r < 4; r++) {
                int n  = qt * 128 + row0 + mt * 16 + (r >> 1) * 8;
                int dh = col0 + nt * 8 + (r & 1);
                size_t o = ((size_t)b * N_ + n) * D_ + h * DH_ + dh;
                __nv_bfloat16 vh, vl; bf_split(acc[mt][nt][r], vh, vl);
                sahi[o] = vh; salo[o] = vl;
            }
        }
    }
}

// ---------------------------------------------------------------------------
extern "C" void kernel_launch(void* const* d_in, const int* in_sizes, int n_in,
                              void* d_out, int out_size)
{
    const float* x     = (const float*)d_in[0];
    const float* Wqkv  = (const float*)d_in[1];
    const float* bqkv  = (const float*)d_in[2];
    const float* Wproj = (const float*)d_in[3];
    const float* bproj = (const float*)d_in[4];
    float* out = (float*)d_out;

    const size_t OUT_ELEMS  = (size_t)B_ * N_ * D_;
    const size_t ATTN_ELEMS = (size_t)B_ * H_ * N_ * N_;

    float* attnp;
    cudaGetSymbolAddress((void**)&attnp, g_attn);
    if ((size_t)out_size >= OUT_ELEMS + ATTN_ELEMS)
        attnp = out + OUT_ELEMS;

    __nv_bfloat16 *xhi, *xlo, *wqhi, *wqlo, *wphi, *wplo, *sahi, *salo;
    __nv_bfloat16 *qh, *ql, *kh, *kl, *vth, *vtl, *pbh, *pbl;
    cudaGetSymbolAddress((void**)&xhi,  g_xhi);
    cudaGetSymbolAddress((void**)&xlo,  g_xlo);
    cudaGetSymbolAddress((void**)&wqhi, g_wqhi);
    cudaGetSymbolAddress((void**)&wqlo, g_wqlo);
    cudaGetSymbolAddress((void**)&wphi, g_wphi);
    cudaGetSymbolAddress((void**)&wplo, g_wplo);
    cudaGetSymbolAddress((void**)&sahi, g_sahi);
    cudaGetSymbolAddress((void**)&salo, g_salo);
    cudaGetSymbolAddress((void**)&qh,   g_qh);
    cudaGetSymbolAddress((void**)&ql,   g_ql);
    cudaGetSymbolAddress((void**)&kh,   g_kh);
    cudaGetSymbolAddress((void**)&kl,   g_kl);
    cudaGetSymbolAddress((void**)&vth,  g_vth);
    cudaGetSymbolAddress((void**)&vtl,  g_vtl);
    cudaGetSymbolAddress((void**)&pbh,  g_pbh);
    cudaGetSymbolAddress((void**)&pbl,  g_pbl);

    cudaFuncSetAttribute(gemm_pipe<0>, cudaFuncAttributeMaxDynamicSharedMemorySize, GP_SMEM);
    cudaFuncSetAttribute(gemm_pipe<1>, cudaFuncAttributeMaxDynamicSharedMemorySize, GP_SMEM);
    cudaFuncSetAttribute(scores_mma,   cudaFuncAttributeMaxDynamicSharedMemorySize, SC_SMEM);
    cudaFuncSetAttribute(sa_pipe,      cudaFuncAttributeMaxDynamicSharedMemorySize, SP_SMEM);

    split_all<<<XBLK + WQBLK + WPBLK, 256>>>(
        x, Wqkv, Wproj, xhi, xlo, wqhi, wqlo, wphi, wplo);

    gemm_pipe<0><<<dim3(M_ / 128, J3_ / 128), 256, GP_SMEM>>>(
        xhi, xlo, wqhi, wqlo, bqkv, nullptr, kh, kl, qh, ql, vth, vtl);

    scores_mma<<<dim3(N_ / 128, N_ / 128, B_ * H_), 256, SC_SMEM>>>(
        qh, ql, kh, kl, attnp);

    softmax2<<<B_ * H_ * N_, 256>>>(attnp, pbh, pbl);

    sa_pipe<<<dim3(B_ * H_, N_ / 128), 256, SP_SMEM>>>(
        pbh, pbl, vth, vtl, sahi, salo);

    gemm_pipe<1><<<dim3(M_ / 128, D_ / 128), 256, GP_SMEM>>>(
        sahi, salo, wphi, wplo, bproj, out,
        nullptr, nullptr, nullptr, nullptr, nullptr, nullptr);
}